// round 15
// baseline (speedup 1.0000x reference)
#include <cuda_runtime.h>
#include <cuda_fp16.h>
#include <cstdint>

#define BB     4
#define SQL    2048
#define SKL    2048
#define DMODEL 1024
#define NH     16
#define HDIM   64
#define NKMAX  2048

#define NIN  ((size_t)BB * SQL * DMODEL)
#define NW   ((size_t)DMODEL * DMODEL)

// Pre-converted sources (all single fp16)
__device__ __half g_qsh[NIN];
__device__ __half g_ksh[NIN];
__device__ __half g_vsh[NIN];
__device__ __half g_wqh[NW];
__device__ __half g_wkh[NW];
__device__ __half g_wvh[NW];
__device__ __half g_woh[NW];
// Projected tensors
__device__ __half g_Qhi[NIN];               // Q fp16 (0.125*log2e folded)
__device__ __half g_Khi[NIN];               // K compacted fp16
__device__ __half g_Vc [NIN];               // V compacted fp16
__device__ __half g_Vthi[(size_t)BB * NH * HDIM * NKMAX];
__device__ __half g_AOhi[NIN];              // attention out fp16
__device__ int g_rowmap[BB * SKL];
__device__ int g_knum[BB];

// ===========================================================================
// PTX helpers
// ===========================================================================
__device__ __forceinline__ void mma16816(float c[4],
                                         uint32_t a0, uint32_t a1,
                                         uint32_t a2, uint32_t a3,
                                         uint32_t b0, uint32_t b1) {
    asm volatile(
        "mma.sync.aligned.m16n8k16.row.col.f32.f16.f16.f32 "
        "{%0,%1,%2,%3}, {%4,%5,%6,%7}, {%8,%9}, {%0,%1,%2,%3};"
        : "+f"(c[0]), "+f"(c[1]), "+f"(c[2]), "+f"(c[3])
        : "r"(a0), "r"(a1), "r"(a2), "r"(a3), "r"(b0), "r"(b1));
}

__device__ __forceinline__ void ldm_x4(uint32_t* r, uint32_t saddr) {
    asm volatile(
        "ldmatrix.sync.aligned.m8n8.x4.shared.b16 {%0,%1,%2,%3}, [%4];"
        : "=r"(r[0]), "=r"(r[1]), "=r"(r[2]), "=r"(r[3]) : "r"(saddr));
}

__device__ __forceinline__ uint32_t s2u(const void* p) {
    return (uint32_t)__cvta_generic_to_shared(p);
}

__device__ __forceinline__ uint32_t pack_h2(float a, float b) {
    __half2 h = __floats2half2_rn(a, b);
    return *(uint32_t*)&h;
}

// ===========================================================================
// Preps
// ===========================================================================
__global__ __launch_bounds__(256) void prep_in(
    const float* __restrict__ q, const float* __restrict__ k,
    const float* __restrict__ v)
{
    const size_t i = (size_t)blockIdx.x * 256 + threadIdx.x;
    const float* src = (blockIdx.y == 0) ? q : (blockIdx.y == 1) ? k : v;
    __half* dst = (blockIdx.y == 0) ? g_qsh : (blockIdx.y == 1) ? g_ksh : g_vsh;
    float4 x = *(const float4*)(src + i * 4);
    uint2 h; h.x = pack_h2(x.x, x.y); h.y = pack_h2(x.z, x.w);
    *(uint2*)(dst + i * 4) = h;
}

__global__ __launch_bounds__(256) void prep_w(
    const float* __restrict__ wq, const float* __restrict__ wk,
    const float* __restrict__ wv, const float* __restrict__ wo)
{
    const size_t i = (size_t)blockIdx.x * 256 + threadIdx.x;
    const float* src = (blockIdx.y == 0) ? wq : (blockIdx.y == 1) ? wk
                      : (blockIdx.y == 2) ? wv : wo;
    __half* dst = (blockIdx.y == 0) ? g_wqh : (blockIdx.y == 1) ? g_wkh
                 : (blockIdx.y == 2) ? g_wvh : g_woh;
    float4 x = *(const float4*)(src + i * 4);
    uint2 h; h.x = pack_h2(x.x, x.y); h.y = pack_h2(x.z, x.w);
    *(uint2*)(dst + i * 4) = h;
}

__global__ __launch_bounds__(256) void scan_mask(const int* __restrict__ kpm) {
    const int b = blockIdx.x, t = threadIdx.x;
    __shared__ int cnt[256];
    int loc[8], c = 0;
#pragma unroll
    for (int i = 0; i < 8; i++) {
        loc[i] = (kpm[b * SKL + t * 8 + i] != 0) ? 1 : 0;
        c += loc[i];
    }
    cnt[t] = c;
    __syncthreads();
    for (int off = 1; off < 256; off <<= 1) {
        int v = (t >= off) ? cnt[t - off] : 0;
        __syncthreads();
        cnt[t] += v;
        __syncthreads();
    }
    int pos = cnt[t] - c;
#pragma unroll
    for (int i = 0; i < 8; i++) g_rowmap[b * SKL + t * 8 + i] = -1;
    __syncthreads();
#pragma unroll
    for (int i = 0; i < 8; i++) {
        if (loc[i]) g_rowmap[b * SKL + pos++] = b * SKL + t * 8 + i;
    }
    if (t == 255) g_knum[b] = cnt[255];
}

// ===========================================================================
// GEMM body: single-term fp16, CTA tile 256x128, 8 warps in 4x2
// (warp tile 64x64). LDG->reg prefetch, STS, 2-buffer, 1 sync/stage.
// ===========================================================================
#define LDSROW 40
#define A_ARR  (256 * LDSROW)      // A tile: 256 rows (halves)
#define B_ARR  (128 * LDSROW)      // B tile: 128 rows
#define G_BUF  (A_ARR + B_ARR)     // halves per buffer
#define G1_SMEM (2 * G_BUF * 2)    // 61440 bytes

__device__ __forceinline__ void g_ldg1(
    const __half* Ah, const __half* Wh,
    bool av, size_t aoff, size_t boff, int k0, uint4* rg)
{
    if (av) {
        rg[0] = *(const uint4*)(Ah + aoff + k0);
        rg[1] = *(const uint4*)(Ah + aoff + k0 + 8);
        rg[2] = *(const uint4*)(Ah + aoff + k0 + 16);
        rg[3] = *(const uint4*)(Ah + aoff + k0 + 24);
    } else {
        rg[0] = rg[1] = rg[2] = rg[3] = make_uint4(0u, 0u, 0u, 0u);
    }
    rg[4] = *(const uint4*)(Wh + boff + k0);
    rg[5] = *(const uint4*)(Wh + boff + k0 + 8);
}

__device__ __forceinline__ void g_sts1(__half* buf, int arow, int brow,
                                       int bcol, const uint4* rg)
{
    const int oa = arow * LDSROW;
    *(uint4*)&buf[oa]      = rg[0];
    *(uint4*)&buf[oa + 8]  = rg[1];
    *(uint4*)&buf[oa + 16] = rg[2];
    *(uint4*)&buf[oa + 24] = rg[3];
    const int ob = A_ARR + brow * LDSROW + bcol;
    *(uint4*)&buf[ob]     = rg[4];
    *(uint4*)&buf[ob + 8] = rg[5];
}

__device__ __forceinline__ void gemm_body1(
    const __half* __restrict__ Ah, const __half* __restrict__ Wh,
    const float* __restrict__ bias,
    float* __restrict__ Cf, __half* __restrict__ Chi,
    float oscale, const int* __restrict__ rowmap, __half* gsm)
{
    const int tid  = threadIdx.x;
    const int w    = tid >> 5;
    const int lane = tid & 31;
    const int gid  = lane >> 2;
    const int tig  = lane & 3;
    const int bm   = blockIdx.y * 256;
    const int bn   = blockIdx.x * 128;
    const int wm = (w >> 1) * 64;     // 0,64,128,192
    const int wn = (w & 1) * 64;      // 0,64

    float acc[4][8][4];
#pragma unroll
    for (int i = 0; i < 4; i++)
#pragma unroll
        for (int j = 0; j < 8; j++)
#pragma unroll
            for (int k = 0; k < 4; k++) acc[i][j][k] = 0.f;

    // A: thread t loads row t (32 halves); B: row t>>1, half (t&1)*16
    const int arow = tid;
    const int brow = tid >> 1;
    const int bcol = (tid & 1) * 16;
    int srow = bm + arow;
    if (rowmap) srow = rowmap[srow];
    const bool avalid = (srow >= 0);
    const size_t aoff = (size_t)(avalid ? srow : 0) * 1024;
    const size_t boff = (size_t)(bn + brow) * 1024 + bcol;

    const uint32_t sb = s2u(gsm);
    const int aoffL = (wm + (lane & 15)) * LDSROW + (lane >> 4) * 8;
    const int boffL = (wn + ((lane & 7) | ((lane >> 1) & 8))) * LDSROW
                      + ((lane >> 3) & 1) * 8;

    uint4 rg[6];
    g_ldg1(Ah, Wh, avalid, aoff, boff, 0, rg);
    g_sts1(gsm, arow, brow, bcol, rg);

    for (int s = 0; s < 32; s++) {
        __syncthreads();
        if (s < 31) g_ldg1(Ah, Wh, avalid, aoff, boff, (s + 1) * 32, rg);

        const uint32_t base = sb + ((s & 1) ? (uint32_t)(G_BUF * 2) : 0u);

#pragma unroll
        for (int ks = 0; ks < 2; ks++) {
            const int kb = ks * 16;
            uint32_t A[4][4];
#pragma unroll
            for (int am = 0; am < 4; am++)
                ldm_x4(A[am], base + (uint32_t)((aoffL + am * 16 * LDSROW + kb) * 2));
            uint32_t B[4][4];
#pragma unroll
            for (int pr = 0; pr < 4; pr++)
                ldm_x4(B[pr], base + (uint32_t)(A_ARR * 2)
                                  + (uint32_t)((boffL + pr * 16 * LDSROW + kb) * 2));
#pragma unroll
            for (int am = 0; am < 4; am++)
#pragma unroll
                for (int an = 0; an < 8; an++) {
                    mma16816(acc[am][an],
                             A[am][0], A[am][1], A[am][2], A[am][3],
                             B[an >> 1][(an & 1) * 2],
                             B[an >> 1][(an & 1) * 2 + 1]);
                }
        }
        if (s < 31) g_sts1(gsm + ((s + 1) & 1) * G_BUF, arow, brow, bcol, rg);
    }

    // Epilogue
#pragma unroll
    for (int am = 0; am < 4; am++) {
        const int row = bm + wm + am * 16 + gid;
        bool v0 = true, v1 = true;
        if (rowmap) {
            v0 = (rowmap[row] >= 0);
            v1 = (rowmap[row + 8] >= 0);
        }
#pragma unroll
        for (int an = 0; an < 8; an++) {
            const int col = bn + wn + an * 8 + tig * 2;
            const float b0 = bias[col], b1 = bias[col + 1];
            float o00 = v0 ? (acc[am][an][0] + b0) * oscale : 0.f;
            float o01 = v0 ? (acc[am][an][1] + b1) * oscale : 0.f;
            float o10 = v1 ? (acc[am][an][2] + b0) * oscale : 0.f;
            float o11 = v1 ? (acc[am][an][3] + b1) * oscale : 0.f;
            if (Chi) {
                *(uint32_t*)&Chi[(size_t)row * 1024 + col] = pack_h2(o00, o01);
                *(uint32_t*)&Chi[(size_t)(row + 8) * 1024 + col] = pack_h2(o10, o11);
            } else {
                float2 f0 = {o00, o01}, f1 = {o10, o11};
                *(float2*)(Cf + (size_t)row * 1024 + col) = f0;
                *(float2*)(Cf + (size_t)(row + 8) * 1024 + col) = f1;
            }
        }
    }
}

// Fused Q/K/V projections (single-term fp16, one launch).
__global__ __launch_bounds__(256) void qkv_gemm(
    const float* __restrict__ bq, const float* __restrict__ bk,
    const float* __restrict__ bv)
{
    extern __shared__ __half gsm[];
    if (blockIdx.z == 0) {
        gemm_body1(g_qsh, g_wqh, bq, nullptr, g_Qhi,
                   0.125f * 1.44269504f, nullptr, gsm);
    } else if (blockIdx.z == 1) {
        gemm_body1(g_ksh, g_wkh, bk, nullptr, g_Khi, 1.0f, g_rowmap, gsm);
    } else {
        gemm_body1(g_vsh, g_wvh, bv, nullptr, g_Vc, 1.0f, g_rowmap, gsm);
    }
}

// O projection: single-term, f32 out.
__global__ __launch_bounds__(256) void o_gemm(
    const float* __restrict__ bo, float* __restrict__ out)
{
    extern __shared__ __half gsm[];
    gemm_body1(g_AOhi, g_woh, bo, out, nullptr, 1.0f, nullptr, gsm);
}

// ===========================================================================
// Prep: V transpose (fp16 in -> fp16 out) -> Vt[b][h][d][key]
// ===========================================================================
__global__ __launch_bounds__(256) void prep_vt() {
    const int b = blockIdx.z, h = blockIdx.y, j0 = blockIdx.x * 64;
    const int nv  = g_knum[b];
    const int nkp = (nv + 63) & ~63;
    if (j0 >= nkp) return;
    __shared__ __half tile[64][72];
    const int t = threadIdx.x;
#pragma unroll
    for (int p = 0; p < 2; p++) {
        const int r = p * 32 + (t >> 3);
        const int c = (t & 7) * 8;
        uint4 v = *(const uint4*)&g_Vc[((size_t)b * SKL + j0 + r) * 1024 + h * 64 + c];
        *(uint4*)&tile[r][c] = v;
    }
    __syncthreads();
    const int d = t >> 2, jg = (t & 3) * 16;
    ushort hi[16];
#pragma unroll
    for (int i = 0; i < 16; i++) hi[i] = *(ushort*)&tile[jg + i][d];
    const size_t base = (((size_t)(b * NH + h)) * 64 + d) * NKMAX + j0 + jg;
    *(uint4*)&g_Vthi[base]     = *(uint4*)hi;
    *(uint4*)&g_Vthi[base + 8] = *(uint4*)&hi[8];
}

// ===========================================================================
// Flash attention: single-fp16 S and PV; exp2 softmax; 2-buffer K/V.
// ===========================================================================
#define FLDS   72
#define F_CH   (64 * FLDS)
#define F_BUF2 (2 * F_CH)
#define F_SMEM (2 * F_BUF2 * 2)   // 36864 bytes

__device__ __forceinline__ void f_ldg(int b, int h, int kt, int r, int c0,
                                      uint4* rg) {
    const size_t kb = ((size_t)b * SKL + kt + r) * 1024 + h * 64 + c0;
    rg[0] = *(const uint4*)&g_Khi[kb];
    rg[1] = *(const uint4*)&g_Khi[kb + 8];
    const size_t vb = (((size_t)(b * NH + h)) * 64 + r) * NKMAX + kt + c0;
    rg[2] = *(const uint4*)&g_Vthi[vb];
    rg[3] = *(const uint4*)&g_Vthi[vb + 8];
}

__device__ __forceinline__ void f_sts(__half* buf, int r, int c0,
                                      const uint4* rg) {
    const int o = r * FLDS + c0;
    *(uint4*)&buf[o]            = rg[0];
    *(uint4*)&buf[o + 8]        = rg[1];
    *(uint4*)&buf[F_CH + o]     = rg[2];
    *(uint4*)&buf[F_CH + o + 8] = rg[3];
}

__global__ __launch_bounds__(256) void flash_tc() {
    extern __shared__ __half fsm[];

    const int b = blockIdx.z, h = blockIdx.y, q0 = blockIdx.x * 128;
    const int tid = threadIdx.x;
    const int w = tid >> 5, lane = tid & 31;
    const int gid = lane >> 2, tig = lane & 3;

    const int nv  = g_knum[b];
    const int nkp = (nv + 63) & ~63;

    // ---- Stage Q through buffer 0 ----
    {
        const int r = tid >> 1, c0 = (tid & 1) * 32;
        const size_t gbase = ((size_t)b * SQL + q0 + r) * 1024 + h * 64 + c0;
        __half* qh = fsm + r * FLDS + c0;
#pragma unroll
        for (int u = 0; u < 4; u++)
            *(uint4*)&qh[u * 8] = *(const uint4*)&g_Qhi[gbase + u * 8];
    }
    __syncthreads();

    const uint32_t fb = s2u(fsm);
    uint32_t Qh[4][4];
    {
        const int qoffL = (w * 16 + (lane & 15)) * FLDS + (lane >> 4) * 8;
#pragma unroll
        for (int ks = 0; ks < 4; ks++)
            ldm_x4(Qh[ks], fb + (uint32_t)((qoffL + ks * 16) * 2));
    }
    __syncthreads();

    float Oa[8][4];
#pragma unroll
    for (int i = 0; i < 8; i++)
#pragma unroll
        for (int j = 0; j < 4; j++) Oa[i][j] = 0.f;
    float m0 = -1e30f, m1 = -1e30f, l0 = 0.f, l1 = 0.f;

    const int lr = tid >> 2, lc0 = (tid & 3) * 16;
    const int foffL = ((lane & 7) | ((lane >> 1) & 8)) * FLDS
                      + ((lane >> 3) & 1) * 8;
    uint4 rg[4];
    f_ldg(b, h, 0, lr, lc0, rg);
    f_sts(fsm, lr, lc0, rg);

    int par = 0;
    for (int kt = 0; kt < nkp; kt += 64, par ^= 1) {
        __syncthreads();
        const bool more = (kt + 64) < nkp;
        if (more) f_ldg(b, h, kt + 64, lr, lc0, rg);

        const uint32_t base = fb + (uint32_t)(par * F_BUF2 * 2);

        // ---- S = Q K^T ----
        float S[8][4];
#pragma unroll
        for (int i = 0; i < 8; i++)
#pragma unroll
            for (int j = 0; j < 4; j++) S[i][j] = 0.f;

#pragma unroll
        for (int ks = 0; ks < 4; ks++) {
            const int kb = ks * 16;
#pragma unroll
            for (int pr = 0; pr < 4; pr++) {
                uint32_t kh[4];
                ldm_x4(kh, base + (uint32_t)((foffL + pr * 16 * FLDS + kb) * 2));
#pragma unroll
                for (int t2 = 0; t2 < 2; t2++) {
                    mma16816(S[pr * 2 + t2],
                             Qh[ks][0], Qh[ks][1], Qh[ks][2], Qh[ks][3],
                             kh[t2 * 2], kh[t2 * 2 + 1]);
                }
            }
        }

        // ---- tail mask ----
        if (kt + 64 > nv) {
#pragma unroll
            for (int nt = 0; nt < 8; nt++) {
                const int col = kt + nt * 8 + tig * 2;
                if (col >= nv)     { S[nt][0] = -1e30f; S[nt][2] = -1e30f; }
                if (col + 1 >= nv) { S[nt][1] = -1e30f; S[nt][3] = -1e30f; }
            }
        }

        // ---- online softmax (log2 domain) ----
        float mx0 = -1e30f, mx1 = -1e30f;
#pragma unroll
        for (int nt = 0; nt < 8; nt++) {
            mx0 = fmaxf(mx0, fmaxf(S[nt][0], S[nt][1]));
            mx1 = fmaxf(mx1, fmaxf(S[nt][2], S[nt][3]));
        }
        mx0 = fmaxf(mx0, __shfl_xor_sync(0xffffffffu, mx0, 1));
        mx0 = fmaxf(mx0, __shfl_xor_sync(0xffffffffu, mx0, 2));
        mx1 = fmaxf(mx1, __shfl_xor_sync(0xffffffffu, mx1, 1));
        mx1 = fmaxf(mx1, __shfl_xor_sync(0xffffffffu, mx1, 2));

        const float mn0 = fmaxf(m0, mx0), mn1 = fmaxf(m1, mx1);
        const float corr0 = exp2f(m0 - mn0), corr1 = exp2f(m1 - mn1);
        m0 = mn0; m1 = mn1;

        float sum0 = 0.f, sum1 = 0.f;
        uint32_t Ph[4][4];
#pragma unroll
        for (int nt = 0; nt < 8; nt++) {
            const float p0 = exp2f(S[nt][0] - m0);
            const float p1 = exp2f(S[nt][1] - m0);
            const float p2 = exp2f(S[nt][2] - m1);
            const float p3 = exp2f(S[nt][3] - m1);
            sum0 += p0 + p1; sum1 += p2 + p3;
            const uint32_t hi01 = pack_h2(p0, p1);
            const uint32_t hi23 = pack_h2(p2, p3);
            const int ks = nt >> 1;
            if ((nt & 1) == 0) {
                Ph[ks][0] = hi01; Ph[ks][1] = hi23;
            } else {
                Ph[ks][2] = hi01; Ph[ks][3] = hi23;
            }
        }
        sum0 += __shfl_xor_sync(0xffffffffu, sum0, 1);
        sum0 += __shfl_xor_sync(0xffffffffu, sum0, 2);
        sum1 += __shfl_xor_sync(0xffffffffu, sum1, 1);
        sum1 += __shfl_xor_sync(0xffffffffu, sum1, 2);
        l0 = l0 * corr0 + sum0;
        l1 = l1 * corr1 + sum1;

#pragma unroll
        for (int nt = 0; nt < 8; nt++) {
            Oa[nt][0] *= corr0; Oa[nt][1] *= corr0;
            Oa[nt][2] *= corr1; Oa[nt][3] *= corr1;
        }

        // ---- O += P V (single term) ----
#pragma unroll
        for (int ks = 0; ks < 4; ks++) {
            const int kb = ks * 16;
#pragma unroll
            for (int pr = 0; pr < 4; pr++) {
                const uint32_t bd = (uint32_t)((foffL + pr * 16 * FLDS + kb) * 2);
                uint32_t vh[4];
                ldm_x4(vh, base + (uint32_t)(F_CH * 2) + bd);
#pragma unroll
                for (int t2 = 0; t2 < 2; t2++) {
                    mma16816(Oa[pr * 2 + t2],
                             Ph[ks][0], Ph[ks][1], Ph[ks][2], Ph[ks][3],
                             vh[t2 * 2], vh[t2 * 2 + 1]);
                }
            }
        }

        if (more) f_sts(fsm + (par ^ 1) * F_BUF2, lr, lc0, rg);
    }

    // ---- epilogue ----
    const float inv0 = 1.f / l0, inv1 = 1.f / l1;
    const int row0 = q0 + w * 16 + gid;
#pragma unroll
    for (int nt = 0; nt < 8; nt++) {
        const int col = h * 64 + nt * 8 + tig * 2;
        const size_t i0 = ((size_t)b * SQL + row0) * 1024 + col;
        const size_t i1 = ((size_t)b * SQL + row0 + 8) * 1024 + col;
        *(uint32_t*)&g_AOhi[i0] = pack_h2(Oa[nt][0] * inv0, Oa[nt][1] * inv0);
        *(uint32_t*)&g_AOhi[i1] = pack_h2(Oa[nt][2] * inv1, Oa[nt][3] * inv1);
    }
}

// ---------------------------------------------------------------------------
extern "C" void kernel_launch(void* const* d_in, const int* in_sizes, int n_in,
                              void* d_out, int out_size)
{
    const float* query = (const float*)d_in[0];
    const float* key   = (const float*)d_in[1];
    const float* value = (const float*)d_in[2];
    const int*   kpm   = (const int*)  d_in[3];
    const float* Wq    = (const float*)d_in[4];
    const float* bq    = (const float*)d_in[5];
    const float* Wk    = (const float*)d_in[6];
    const float* bk    = (const float*)d_in[7];
    const float* Wv    = (const float*)d_in[8];
    const float* bv    = (const float*)d_in[9];
    const float* Wo    = (const float*)d_in[10];
    const float* bo    = (const float*)d_in[11];
    float* out = (float*)d_out;

    cudaFuncSetAttribute(qkv_gemm, cudaFuncAttributeMaxDynamicSharedMemorySize,
                         G1_SMEM);
    cudaFuncSetAttribute(o_gemm, cudaFuncAttributeMaxDynamicSharedMemorySize,
                         G1_SMEM);
    cudaFuncSetAttribute(flash_tc, cudaFuncAttributeMaxDynamicSharedMemorySize,
                         F_SMEM);

    scan_mask<<<BB, 256>>>(kpm);

    const int gin = (int)(NIN / 1024);
    const int gw  = (int)(NW  / 1024);
    prep_in<<<dim3(gin, 3), 256>>>(query, key, value);
    prep_w<<<dim3(gw, 4), 256>>>(Wq, Wk, Wv, Wo);

    dim3 gQKV(DMODEL / 128, (BB * SQL) / 256, 3);   // (8, 32, 3)
    qkv_gemm<<<gQKV, 256, G1_SMEM>>>(bq, bk, bv);

    prep_vt<<<dim3(SKL / 64, NH, BB), 256>>>();

    flash_tc<<<dim3(SQL / 128, NH, BB), 256, F_SMEM>>>();

    dim3 gO(DMODEL / 128, (BB * SQL) / 256);        // (8, 32)
    o_gemm<<<gO, 256, G1_SMEM>>>(bo, out);
}

// round 16
// speedup vs baseline: 1.0395x; 1.0395x over previous
#include <cuda_runtime.h>
#include <cuda_fp16.h>
#include <cstdint>

#define BB     4
#define SQL    2048
#define SKL    2048
#define DMODEL 1024
#define NH     16
#define HDIM   64
#define NKMAX  2048

#define NIN  ((size_t)BB * SQL * DMODEL)
#define NW   ((size_t)DMODEL * DMODEL)

// Pre-converted sources (all single fp16)
__device__ __half g_qsh[NIN];
__device__ __half g_ksh[NIN];
__device__ __half g_vsh[NIN];
__device__ __half g_wqh[NW];
__device__ __half g_wkh[NW];
__device__ __half g_wvh[NW];
__device__ __half g_woh[NW];
// Projected tensors
__device__ __half g_Qhi[NIN];               // Q fp16 (0.125*log2e folded)
__device__ __half g_Khi[NIN];               // K compacted fp16
__device__ __half g_Vc [NIN];               // V compacted fp16
__device__ __half g_Vthi[(size_t)BB * NH * HDIM * NKMAX];
__device__ __half g_AOhi[NIN];              // attention out fp16
__device__ int g_rowmap[BB * SKL];
__device__ int g_knum[BB];

// ===========================================================================
// PTX helpers
// ===========================================================================
__device__ __forceinline__ void mma16816(float c[4],
                                         uint32_t a0, uint32_t a1,
                                         uint32_t a2, uint32_t a3,
                                         uint32_t b0, uint32_t b1) {
    asm volatile(
        "mma.sync.aligned.m16n8k16.row.col.f32.f16.f16.f32 "
        "{%0,%1,%2,%3}, {%4,%5,%6,%7}, {%8,%9}, {%0,%1,%2,%3};"
        : "+f"(c[0]), "+f"(c[1]), "+f"(c[2]), "+f"(c[3])
        : "r"(a0), "r"(a1), "r"(a2), "r"(a3), "r"(b0), "r"(b1));
}

__device__ __forceinline__ void ldm_x4(uint32_t* r, uint32_t saddr) {
    asm volatile(
        "ldmatrix.sync.aligned.m8n8.x4.shared.b16 {%0,%1,%2,%3}, [%4];"
        : "=r"(r[0]), "=r"(r[1]), "=r"(r[2]), "=r"(r[3]) : "r"(saddr));
}

__device__ __forceinline__ uint32_t s2u(const void* p) {
    return (uint32_t)__cvta_generic_to_shared(p);
}

__device__ __forceinline__ uint32_t pack_h2(float a, float b) {
    __half2 h = __floats2half2_rn(a, b);
    return *(uint32_t*)&h;
}

__device__ __forceinline__ uint32_t h2exp2(uint32_t x) {
    uint32_t r;
    asm("ex2.approx.f16x2 %0, %1;" : "=r"(r) : "r"(x));
    return r;
}

// ===========================================================================
// Preps
// ===========================================================================
__global__ __launch_bounds__(256) void prep_in(
    const float* __restrict__ q, const float* __restrict__ k,
    const float* __restrict__ v)
{
    const size_t i = (size_t)blockIdx.x * 256 + threadIdx.x;
    const float* src = (blockIdx.y == 0) ? q : (blockIdx.y == 1) ? k : v;
    __half* dst = (blockIdx.y == 0) ? g_qsh : (blockIdx.y == 1) ? g_ksh : g_vsh;
    float4 x = *(const float4*)(src + i * 4);
    uint2 h; h.x = pack_h2(x.x, x.y); h.y = pack_h2(x.z, x.w);
    *(uint2*)(dst + i * 4) = h;
}

__global__ __launch_bounds__(256) void prep_w(
    const float* __restrict__ wq, const float* __restrict__ wk,
    const float* __restrict__ wv, const float* __restrict__ wo)
{
    const size_t i = (size_t)blockIdx.x * 256 + threadIdx.x;
    const float* src = (blockIdx.y == 0) ? wq : (blockIdx.y == 1) ? wk
                      : (blockIdx.y == 2) ? wv : wo;
    __half* dst = (blockIdx.y == 0) ? g_wqh : (blockIdx.y == 1) ? g_wkh
                 : (blockIdx.y == 2) ? g_wvh : g_woh;
    float4 x = *(const float4*)(src + i * 4);
    uint2 h; h.x = pack_h2(x.x, x.y); h.y = pack_h2(x.z, x.w);
    *(uint2*)(dst + i * 4) = h;
}

__global__ __launch_bounds__(256) void scan_mask(const int* __restrict__ kpm) {
    const int b = blockIdx.x, t = threadIdx.x;
    __shared__ int cnt[256];
    int loc[8], c = 0;
#pragma unroll
    for (int i = 0; i < 8; i++) {
        loc[i] = (kpm[b * SKL + t * 8 + i] != 0) ? 1 : 0;
        c += loc[i];
    }
    cnt[t] = c;
    __syncthreads();
    for (int off = 1; off < 256; off <<= 1) {
        int v = (t >= off) ? cnt[t - off] : 0;
        __syncthreads();
        cnt[t] += v;
        __syncthreads();
    }
    int pos = cnt[t] - c;
#pragma unroll
    for (int i = 0; i < 8; i++) g_rowmap[b * SKL + t * 8 + i] = -1;
    __syncthreads();
#pragma unroll
    for (int i = 0; i < 8; i++) {
        if (loc[i]) g_rowmap[b * SKL + pos++] = b * SKL + t * 8 + i;
    }
    if (t == 255) g_knum[b] = cnt[255];
}

// ===========================================================================
// GEMM body: single-term fp16, CTA 128x128, 8 warps 2x4 (warp 64x32).
// R14-proven config (regs ~127 -> 2 CTAs/SM).
// ===========================================================================
#define LDSROW 40
#define G_ARR  (128 * LDSROW)
#define G1_SMEM (2 * 2 * G_ARR * 2)   // 40960

__device__ __forceinline__ void g_ldg1(
    const __half* Ah, const __half* Wh,
    bool av, size_t aoff, size_t boff, int k0, uint4* rg)
{
    if (av) {
        rg[0] = *(const uint4*)(Ah + aoff + k0);
        rg[1] = *(const uint4*)(Ah + aoff + k0 + 8);
    } else {
        rg[0] = rg[1] = make_uint4(0u, 0u, 0u, 0u);
    }
    rg[2] = *(const uint4*)(Wh + boff + k0);
    rg[3] = *(const uint4*)(Wh + boff + k0 + 8);
}

__device__ __forceinline__ void g_sts1(__half* buf, int lrow, int lcol,
                                       const uint4* rg)
{
    const int o = lrow * LDSROW + lcol;
    *(uint4*)&buf[o]             = rg[0];
    *(uint4*)&buf[o + 8]         = rg[1];
    *(uint4*)&buf[G_ARR + o]     = rg[2];
    *(uint4*)&buf[G_ARR + o + 8] = rg[3];
}

__device__ __forceinline__ void gemm_body1(
    const __half* __restrict__ Ah, const __half* __restrict__ Wh,
    const float* __restrict__ bias,
    float* __restrict__ Cf, __half* __restrict__ Chi,
    float oscale, const int* __restrict__ rowmap, __half* gsm)
{
    const int tid  = threadIdx.x;
    const int w    = tid >> 5;
    const int lane = tid & 31;
    const int gid  = lane >> 2;
    const int tig  = lane & 3;
    const int bm   = blockIdx.y * 128;
    const int bn   = blockIdx.x * 128;
    const int wm = (w & 1) * 64;
    const int wn = (w >> 1) * 32;

    float acc[4][4][4];
#pragma unroll
    for (int i = 0; i < 4; i++)
#pragma unroll
        for (int j = 0; j < 4; j++)
#pragma unroll
            for (int k = 0; k < 4; k++) acc[i][j][k] = 0.f;

    const int lrow = tid >> 1;
    const int lcol = (tid & 1) * 16;
    int srow = bm + lrow;
    if (rowmap) srow = rowmap[srow];
    const bool avalid = (srow >= 0);
    const size_t aoff = (size_t)(avalid ? srow : 0) * 1024 + lcol;
    const size_t boff = (size_t)(bn + lrow) * 1024 + lcol;

    const uint32_t sb = s2u(gsm);
    const int aoffL = (wm + (lane & 15)) * LDSROW + (lane >> 4) * 8;
    const int boffL = (wn + ((lane & 7) | ((lane >> 1) & 8))) * LDSROW
                      + ((lane >> 3) & 1) * 8;

    uint4 rg[4];
    g_ldg1(Ah, Wh, avalid, aoff, boff, 0, rg);
    g_sts1(gsm, lrow, lcol, rg);

    for (int s = 0; s < 32; s++) {
        __syncthreads();
        if (s < 31) g_ldg1(Ah, Wh, avalid, aoff, boff, (s + 1) * 32, rg);

        const uint32_t base = sb + ((s & 1) ? (uint32_t)(2 * G_ARR * 2) : 0u);

#pragma unroll
        for (int ks = 0; ks < 2; ks++) {
            const int kb = ks * 16;
            uint32_t A[4][4];
#pragma unroll
            for (int am = 0; am < 4; am++)
                ldm_x4(A[am], base + (uint32_t)((aoffL + am * 16 * LDSROW + kb) * 2));
            uint32_t Bh[8];
#pragma unroll
            for (int pr = 0; pr < 2; pr++) {
                const uint32_t bd = (uint32_t)((boffL + pr * 16 * LDSROW + kb) * 2);
                ldm_x4(&Bh[pr * 4], base + (uint32_t)(G_ARR * 2) + bd);
            }
#pragma unroll
            for (int am = 0; am < 4; am++)
#pragma unroll
                for (int an = 0; an < 4; an++) {
                    mma16816(acc[am][an],
                             A[am][0], A[am][1], A[am][2], A[am][3],
                             Bh[an * 2], Bh[an * 2 + 1]);
                }
        }
        if (s < 31) g_sts1(gsm + ((s + 1) & 1) * 2 * G_ARR, lrow, lcol, rg);
    }

    // Epilogue
#pragma unroll
    for (int am = 0; am < 4; am++) {
        const int row = bm + wm + am * 16 + gid;
        bool v0 = true, v1 = true;
        if (rowmap) {
            v0 = (rowmap[row] >= 0);
            v1 = (rowmap[row + 8] >= 0);
        }
#pragma unroll
        for (int an = 0; an < 4; an++) {
            const int col = bn + wn + an * 8 + tig * 2;
            const float b0 = bias[col], b1 = bias[col + 1];
            float o00 = v0 ? (acc[am][an][0] + b0) * oscale : 0.f;
            float o01 = v0 ? (acc[am][an][1] + b1) * oscale : 0.f;
            float o10 = v1 ? (acc[am][an][2] + b0) * oscale : 0.f;
            float o11 = v1 ? (acc[am][an][3] + b1) * oscale : 0.f;
            if (Chi) {
                *(uint32_t*)&Chi[(size_t)row * 1024 + col] = pack_h2(o00, o01);
                *(uint32_t*)&Chi[(size_t)(row + 8) * 1024 + col] = pack_h2(o10, o11);
            } else {
                float2 f0 = {o00, o01}, f1 = {o10, o11};
                *(float2*)(Cf + (size_t)row * 1024 + col) = f0;
                *(float2*)(Cf + (size_t)(row + 8) * 1024 + col) = f1;
            }
        }
    }
}

// Fused Q/K/V projections.
__global__ __launch_bounds__(256) void qkv_gemm(
    const float* __restrict__ bq, const float* __restrict__ bk,
    const float* __restrict__ bv)
{
    extern __shared__ __half gsm[];
    if (blockIdx.z == 0) {
        gemm_body1(g_qsh, g_wqh, bq, nullptr, g_Qhi,
                   0.125f * 1.44269504f, nullptr, gsm);
    } else if (blockIdx.z == 1) {
        gemm_body1(g_ksh, g_wkh, bk, nullptr, g_Khi, 1.0f, g_rowmap, gsm);
    } else {
        gemm_body1(g_vsh, g_wvh, bv, nullptr, g_Vc, 1.0f, g_rowmap, gsm);
    }
}

// O projection: f32 out.
__global__ __launch_bounds__(256) void o_gemm(
    const float* __restrict__ bo, float* __restrict__ out)
{
    extern __shared__ __half gsm[];
    gemm_body1(g_AOhi, g_woh, bo, out, nullptr, 1.0f, nullptr, gsm);
}

// ===========================================================================
// Prep: V transpose (fp16 -> fp16) -> Vt[b][h][d][key]
// ===========================================================================
__global__ __launch_bounds__(256) void prep_vt() {
    const int b = blockIdx.z, h = blockIdx.y, j0 = blockIdx.x * 64;
    const int nv  = g_knum[b];
    const int nkp = (nv + 63) & ~63;
    if (j0 >= nkp) return;
    __shared__ __half tile[64][72];
    const int t = threadIdx.x;
#pragma unroll
    for (int p = 0; p < 2; p++) {
        const int r = p * 32 + (t >> 3);
        const int c = (t & 7) * 8;
        uint4 v = *(const uint4*)&g_Vc[((size_t)b * SKL + j0 + r) * 1024 + h * 64 + c];
        *(uint4*)&tile[r][c] = v;
    }
    __syncthreads();
    const int d = t >> 2, jg = (t & 3) * 16;
    ushort hi[16];
#pragma unroll
    for (int i = 0; i < 16; i++) hi[i] = *(ushort*)&tile[jg + i][d];
    const size_t base = (((size_t)(b * NH + h)) * 64 + d) * NKMAX + j0 + jg;
    *(uint4*)&g_Vthi[base]     = *(uint4*)hi;
    *(uint4*)&g_Vthi[base + 8] = *(uint4*)&hi[8];
}

// ===========================================================================
// Flash attention: single-fp16 S + PV; half2-exp softmax; l via ones-MMA.
// ===========================================================================
#define FLDS   72
#define F_CH   (64 * FLDS)
#define F_BUF2 (2 * F_CH)
#define F_SMEM (2 * F_BUF2 * 2)   // 36864 bytes

#define ONES_H2 0x3C003C00u       // (1.0h, 1.0h)

__device__ __forceinline__ void f_ldg(int b, int h, int kt, int r, int c0,
                                      uint4* rg) {
    const size_t kb = ((size_t)b * SKL + kt + r) * 1024 + h * 64 + c0;
    rg[0] = *(const uint4*)&g_Khi[kb];
    rg[1] = *(const uint4*)&g_Khi[kb + 8];
    const size_t vb = (((size_t)(b * NH + h)) * 64 + r) * NKMAX + kt + c0;
    rg[2] = *(const uint4*)&g_Vthi[vb];
    rg[3] = *(const uint4*)&g_Vthi[vb + 8];
}

__device__ __forceinline__ void f_sts(__half* buf, int r, int c0,
                                      const uint4* rg) {
    const int o = r * FLDS + c0;
    *(uint4*)&buf[o]            = rg[0];
    *(uint4*)&buf[o + 8]        = rg[1];
    *(uint4*)&buf[F_CH + o]     = rg[2];
    *(uint4*)&buf[F_CH + o + 8] = rg[3];
}

__global__ __launch_bounds__(256) void flash_tc() {
    extern __shared__ __half fsm[];

    const int b = blockIdx.z, h = blockIdx.y, q0 = blockIdx.x * 128;
    const int tid = threadIdx.x;
    const int w = tid >> 5, lane = tid & 31;
    const int gid = lane >> 2, tig = lane & 3;

    const int nv  = g_knum[b];
    const int nkp = (nv + 63) & ~63;

    // ---- Stage Q through buffer 0 ----
    {
        const int r = tid >> 1, c0 = (tid & 1) * 32;
        const size_t gbase = ((size_t)b * SQL + q0 + r) * 1024 + h * 64 + c0;
        __half* qh = fsm + r * FLDS + c0;
#pragma unroll
        for (int u = 0; u < 4; u++)
            *(uint4*)&qh[u * 8] = *(const uint4*)&g_Qhi[gbase + u * 8];
    }
    __syncthreads();

    const uint32_t fb = s2u(fsm);
    uint32_t Qh[4][4];
    {
        const int qoffL = (w * 16 + (lane & 15)) * FLDS + (lane >> 4) * 8;
#pragma unroll
        for (int ks = 0; ks < 4; ks++)
            ldm_x4(Qh[ks], fb + (uint32_t)((qoffL + ks * 16) * 2));
    }
    __syncthreads();

    float Oa[8][4];
#pragma unroll
    for (int i = 0; i < 8; i++)
#pragma unroll
        for (int j = 0; j < 4; j++) Oa[i][j] = 0.f;
    float La[4];
#pragma unroll
    for (int j = 0; j < 4; j++) La[j] = 0.f;
    float m0 = -1e30f, m1 = -1e30f;

    const int lr = tid >> 2, lc0 = (tid & 3) * 16;
    const int foffL = ((lane & 7) | ((lane >> 1) & 8)) * FLDS
                      + ((lane >> 3) & 1) * 8;
    uint4 rg[4];
    f_ldg(b, h, 0, lr, lc0, rg);
    f_sts(fsm, lr, lc0, rg);

    int par = 0;
    for (int kt = 0; kt < nkp; kt += 64, par ^= 1) {
        __syncthreads();
        const bool more = (kt + 64) < nkp;
        if (more) f_ldg(b, h, kt + 64, lr, lc0, rg);

        const uint32_t base = fb + (uint32_t)(par * F_BUF2 * 2);

        // ---- S = Q K^T ----
        float S[8][4];
#pragma unroll
        for (int i = 0; i < 8; i++)
#pragma unroll
            for (int j = 0; j < 4; j++) S[i][j] = 0.f;

#pragma unroll
        for (int ks = 0; ks < 4; ks++) {
            const int kb = ks * 16;
#pragma unroll
            for (int pr = 0; pr < 4; pr++) {
                uint32_t kh[4];
                ldm_x4(kh, base + (uint32_t)((foffL + pr * 16 * FLDS + kb) * 2));
#pragma unroll
                for (int t2 = 0; t2 < 2; t2++) {
                    mma16816(S[pr * 2 + t2],
                             Qh[ks][0], Qh[ks][1], Qh[ks][2], Qh[ks][3],
                             kh[t2 * 2], kh[t2 * 2 + 1]);
                }
            }
        }

        // ---- tail mask ----
        if (kt + 64 > nv) {
#pragma unroll
            for (int nt = 0; nt < 8; nt++) {
                const int col = kt + nt * 8 + tig * 2;
                if (col >= nv)     { S[nt][0] = -1e30f; S[nt][2] = -1e30f; }
                if (col + 1 >= nv) { S[nt][1] = -1e30f; S[nt][3] = -1e30f; }
            }
        }

        // ---- online softmax (log2 domain; fp16x2 exp) ----
        float mx0 = -1e30f, mx1 = -1e30f;
#pragma unroll
        for (int nt = 0; nt < 8; nt++) {
            mx0 = fmaxf(mx0, fmaxf(S[nt][0], S[nt][1]));
            mx1 = fmaxf(mx1, fmaxf(S[nt][2], S[nt][3]));
        }
        mx0 = fmaxf(mx0, __shfl_xor_sync(0xffffffffu, mx0, 1));
        mx0 = fmaxf(mx0, __shfl_xor_sync(0xffffffffu, mx0, 2));
        mx1 = fmaxf(mx1, __shfl_xor_sync(0xffffffffu, mx1, 1));
        mx1 = fmaxf(mx1, __shfl_xor_sync(0xffffffffu, mx1, 2));

        const float mn0 = fmaxf(m0, mx0), mn1 = fmaxf(m1, mx1);
        const float corr0 = exp2f(m0 - mn0), corr1 = exp2f(m1 - mn1);
        m0 = mn0; m1 = mn1;

        uint32_t Ph[4][4];
#pragma unroll
        for (int nt = 0; nt < 8; nt++) {
            // (S - m) pairs -> half2 -> 2^x (packed P fragment directly)
            const uint32_t p01 = h2exp2(pack_h2(S[nt][0] - m0, S[nt][1] - m0));
            const uint32_t p23 = h2exp2(pack_h2(S[nt][2] - m1, S[nt][3] - m1));
            const int ks = nt >> 1;
            if ((nt & 1) == 0) { Ph[ks][0] = p01; Ph[ks][1] = p23; }
            else               { Ph[ks][2] = p01; Ph[ks][3] = p23; }
        }

#pragma unroll
        for (int nt = 0; nt < 8; nt++) {
            Oa[nt][0] *= corr0; Oa[nt][1] *= corr0;
            Oa[nt][2] *= corr1; Oa[nt][3] *= corr1;
        }
        La[0] *= corr0; La[1] *= corr0;
        La[2] *= corr1; La[3] *= corr1;

        // ---- l += P @ ones (4 MMAs; every output col = row-sum of P) ----
#pragma unroll
        for (int ks = 0; ks < 4; ks++)
            mma16816(La, Ph[ks][0], Ph[ks][1], Ph[ks][2], Ph[ks][3],
                     ONES_H2, ONES_H2);

        // ---- O += P V ----
#pragma unroll
        for (int ks = 0; ks < 4; ks++) {
            const int kb = ks * 16;
#pragma unroll
            for (int pr = 0; pr < 4; pr++) {
                const uint32_t bd = (uint32_t)((foffL + pr * 16 * FLDS + kb) * 2);
                uint32_t vh[4];
                ldm_x4(vh, base + (uint32_t)(F_CH * 2) + bd);
#pragma unroll
                for (int t2 = 0; t2 < 2; t2++) {
                    mma16816(Oa[pr * 2 + t2],
                             Ph[ks][0], Ph[ks][1], Ph[ks][2], Ph[ks][3],
                             vh[t2 * 2], vh[t2 * 2 + 1]);
                }
            }
        }

        if (more) f_sts(fsm + (par ^ 1) * F_BUF2, lr, lc0, rg);
    }

    // ---- epilogue ----
    const float inv0 = 1.f / La[0], inv1 = 1.f / La[2];
    const int row0 = q0 + w * 16 + gid;
#pragma unroll
    for (int nt = 0; nt < 8; nt++) {
        const int col = h * 64 + nt * 8 + tig * 2;
        const size_t i0 = ((size_t)b * SQL + row0) * 1024 + col;
        const size_t i1 = ((size_t)b * SQL + row0 + 8) * 1024 + col;
        *(uint32_t*)&g_AOhi[i0] = pack_h2(Oa[nt][0] * inv0, Oa[nt][1] * inv0);
        *(uint32_t*)&g_AOhi[i1] = pack_h2(Oa[nt][2] * inv1, Oa[nt][3] * inv1);
    }
}

// ---------------------------------------------------------------------------
extern "C" void kernel_launch(void* const* d_in, const int* in_sizes, int n_in,
                              void* d_out, int out_size)
{
    const float* query = (const float*)d_in[0];
    const float* key   = (const float*)d_in[1];
    const float* value = (const float*)d_in[2];
    const int*   kpm   = (const int*)  d_in[3];
    const float* Wq    = (const float*)d_in[4];
    const float* bq    = (const float*)d_in[5];
    const float* Wk    = (const float*)d_in[6];
    const float* bk    = (const float*)d_in[7];
    const float* Wv    = (const float*)d_in[8];
    const float* bv    = (const float*)d_in[9];
    const float* Wo    = (const float*)d_in[10];
    const float* bo    = (const float*)d_in[11];
    float* out = (float*)d_out;

    cudaFuncSetAttribute(qkv_gemm, cudaFuncAttributeMaxDynamicSharedMemorySize,
                         G1_SMEM);
    cudaFuncSetAttribute(o_gemm, cudaFuncAttributeMaxDynamicSharedMemorySize,
                         G1_SMEM);
    cudaFuncSetAttribute(flash_tc, cudaFuncAttributeMaxDynamicSharedMemorySize,
                         F_SMEM);

    scan_mask<<<BB, 256>>>(kpm);

    const int gin = (int)(NIN / 1024);
    const int gw  = (int)(NW  / 1024);
    prep_in<<<dim3(gin, 3), 256>>>(query, key, value);
    prep_w<<<dim3(gw, 4), 256>>>(Wq, Wk, Wv, Wo);

    dim3 gQKV(DMODEL / 128, (BB * SQL) / 128, 3);   // (8, 64, 3)
    qkv_gemm<<<gQKV, 256, G1_SMEM>>>(bq, bk, bv);

    prep_vt<<<dim3(SKL / 64, NH, BB), 256>>>();

    flash_tc<<<dim3(SQL / 128, NH, BB), 256, F_SMEM>>>();

    dim3 gO(DMODEL / 128, (BB * SQL) / 128);        // (8, 64)
    o_gemm<<<gO, 256, G1_SMEM>>>(bo, out);
}

// round 17
// speedup vs baseline: 1.1518x; 1.1080x over previous
#include <cuda_runtime.h>
#include <cuda_fp16.h>
#include <cstdint>

#define BB     4
#define SQL    2048
#define SKL    2048
#define DMODEL 1024
#define NH     16
#define HDIM   64
#define NKMAX  2048

#define NIN  ((size_t)BB * SQL * DMODEL)
#define NW   ((size_t)DMODEL * DMODEL)

// Pre-converted sources (all single fp16)
__device__ __half g_qsh[NIN];
__device__ __half g_ksh[NIN];
__device__ __half g_vsh[NIN];
__device__ __half g_wqh[NW];
__device__ __half g_wkh[NW];
__device__ __half g_wvh[NW];
__device__ __half g_woh[NW];
// Projected tensors
__device__ __half g_Qhi[NIN];               // Q fp16 (0.125*log2e folded)
__device__ __half g_Khi[NIN];               // K compacted fp16
__device__ __half g_Vc [NIN];               // V compacted fp16
__device__ __half g_Vthi[(size_t)BB * NH * HDIM * NKMAX];
__device__ __half g_AOhi[NIN];              // attention out fp16
__device__ int g_rowmap[BB * SKL];
__device__ int g_knum[BB];

// ===========================================================================
// PTX helpers
// ===========================================================================
__device__ __forceinline__ void mma16816(float c[4],
                                         uint32_t a0, uint32_t a1,
                                         uint32_t a2, uint32_t a3,
                                         uint32_t b0, uint32_t b1) {
    asm volatile(
        "mma.sync.aligned.m16n8k16.row.col.f32.f16.f16.f32 "
        "{%0,%1,%2,%3}, {%4,%5,%6,%7}, {%8,%9}, {%0,%1,%2,%3};"
        : "+f"(c[0]), "+f"(c[1]), "+f"(c[2]), "+f"(c[3])
        : "r"(a0), "r"(a1), "r"(a2), "r"(a3), "r"(b0), "r"(b1));
}

__device__ __forceinline__ void ldm_x4(uint32_t* r, uint32_t saddr) {
    asm volatile(
        "ldmatrix.sync.aligned.m8n8.x4.shared.b16 {%0,%1,%2,%3}, [%4];"
        : "=r"(r[0]), "=r"(r[1]), "=r"(r[2]), "=r"(r[3]) : "r"(saddr));
}

__device__ __forceinline__ uint32_t s2u(const void* p) {
    return (uint32_t)__cvta_generic_to_shared(p);
}

__device__ __forceinline__ uint32_t pack_h2(float a, float b) {
    __half2 h = __floats2half2_rn(a, b);
    return *(uint32_t*)&h;
}

__device__ __forceinline__ uint32_t h2exp2(uint32_t x) {
    uint32_t r;
    asm("ex2.approx.f16x2 %0, %1;" : "=r"(r) : "r"(x));
    return r;
}

// ===========================================================================
// Preps
// ===========================================================================
__global__ __launch_bounds__(256) void prep_in(
    const float* __restrict__ q, const float* __restrict__ k,
    const float* __restrict__ v)
{
    const size_t i = (size_t)blockIdx.x * 256 + threadIdx.x;
    const float* src = (blockIdx.y == 0) ? q : (blockIdx.y == 1) ? k : v;
    __half* dst = (blockIdx.y == 0) ? g_qsh : (blockIdx.y == 1) ? g_ksh : g_vsh;
    float4 x = *(const float4*)(src + i * 4);
    uint2 h; h.x = pack_h2(x.x, x.y); h.y = pack_h2(x.z, x.w);
    *(uint2*)(dst + i * 4) = h;
}

__global__ __launch_bounds__(256) void prep_w(
    const float* __restrict__ wq, const float* __restrict__ wk,
    const float* __restrict__ wv, const float* __restrict__ wo)
{
    const size_t i = (size_t)blockIdx.x * 256 + threadIdx.x;
    const float* src = (blockIdx.y == 0) ? wq : (blockIdx.y == 1) ? wk
                      : (blockIdx.y == 2) ? wv : wo;
    __half* dst = (blockIdx.y == 0) ? g_wqh : (blockIdx.y == 1) ? g_wkh
                 : (blockIdx.y == 2) ? g_wvh : g_woh;
    float4 x = *(const float4*)(src + i * 4);
    uint2 h; h.x = pack_h2(x.x, x.y); h.y = pack_h2(x.z, x.w);
    *(uint2*)(dst + i * 4) = h;
}

__global__ __launch_bounds__(256) void scan_mask(const int* __restrict__ kpm) {
    const int b = blockIdx.x, t = threadIdx.x;
    __shared__ int cnt[256];
    int loc[8], c = 0;
#pragma unroll
    for (int i = 0; i < 8; i++) {
        loc[i] = (kpm[b * SKL + t * 8 + i] != 0) ? 1 : 0;
        c += loc[i];
    }
    cnt[t] = c;
    __syncthreads();
    for (int off = 1; off < 256; off <<= 1) {
        int v = (t >= off) ? cnt[t - off] : 0;
        __syncthreads();
        cnt[t] += v;
        __syncthreads();
    }
    int pos = cnt[t] - c;
#pragma unroll
    for (int i = 0; i < 8; i++) g_rowmap[b * SKL + t * 8 + i] = -1;
    __syncthreads();
#pragma unroll
    for (int i = 0; i < 8; i++) {
        if (loc[i]) g_rowmap[b * SKL + pos++] = b * SKL + t * 8 + i;
    }
    if (t == 255) g_knum[b] = cnt[255];
}

// ===========================================================================
// GEMM body: single-term fp16, CTA 128x128, 8 warps 2x4 (warp 64x32).
// ===========================================================================
#define LDSROW 40
#define G_ARR  (128 * LDSROW)
#define G1_SMEM (2 * 2 * G_ARR * 2)   // 40960

__device__ __forceinline__ void g_ldg1(
    const __half* Ah, const __half* Wh,
    bool av, size_t aoff, size_t boff, int k0, uint4* rg)
{
    if (av) {
        rg[0] = *(const uint4*)(Ah + aoff + k0);
        rg[1] = *(const uint4*)(Ah + aoff + k0 + 8);
    } else {
        rg[0] = rg[1] = make_uint4(0u, 0u, 0u, 0u);
    }
    rg[2] = *(const uint4*)(Wh + boff + k0);
    rg[3] = *(const uint4*)(Wh + boff + k0 + 8);
}

__device__ __forceinline__ void g_sts1(__half* buf, int lrow, int lcol,
                                       const uint4* rg)
{
    const int o = lrow * LDSROW + lcol;
    *(uint4*)&buf[o]             = rg[0];
    *(uint4*)&buf[o + 8]         = rg[1];
    *(uint4*)&buf[G_ARR + o]     = rg[2];
    *(uint4*)&buf[G_ARR + o + 8] = rg[3];
}

__device__ __forceinline__ void gemm_body1(
    const __half* __restrict__ Ah, const __half* __restrict__ Wh,
    const float* __restrict__ bias,
    float* __restrict__ Cf, __half* __restrict__ Chi,
    float oscale, const int* __restrict__ rowmap, __half* gsm)
{
    const int tid  = threadIdx.x;
    const int w    = tid >> 5;
    const int lane = tid & 31;
    const int gid  = lane >> 2;
    const int tig  = lane & 3;
    const int bm   = blockIdx.y * 128;
    const int bn   = blockIdx.x * 128;
    const int wm = (w & 1) * 64;
    const int wn = (w >> 1) * 32;

    float acc[4][4][4];
#pragma unroll
    for (int i = 0; i < 4; i++)
#pragma unroll
        for (int j = 0; j < 4; j++)
#pragma unroll
            for (int k = 0; k < 4; k++) acc[i][j][k] = 0.f;

    const int lrow = tid >> 1;
    const int lcol = (tid & 1) * 16;
    int srow = bm + lrow;
    if (rowmap) srow = rowmap[srow];
    const bool avalid = (srow >= 0);
    const size_t aoff = (size_t)(avalid ? srow : 0) * 1024 + lcol;
    const size_t boff = (size_t)(bn + lrow) * 1024 + lcol;

    const uint32_t sb = s2u(gsm);
    const int aoffL = (wm + (lane & 15)) * LDSROW + (lane >> 4) * 8;
    const int boffL = (wn + ((lane & 7) | ((lane >> 1) & 8))) * LDSROW
                      + ((lane >> 3) & 1) * 8;

    uint4 rg[4];
    g_ldg1(Ah, Wh, avalid, aoff, boff, 0, rg);
    g_sts1(gsm, lrow, lcol, rg);

    for (int s = 0; s < 32; s++) {
        __syncthreads();
        if (s < 31) g_ldg1(Ah, Wh, avalid, aoff, boff, (s + 1) * 32, rg);

        const uint32_t base = sb + ((s & 1) ? (uint32_t)(2 * G_ARR * 2) : 0u);

#pragma unroll
        for (int ks = 0; ks < 2; ks++) {
            const int kb = ks * 16;
            uint32_t A[4][4];
#pragma unroll
            for (int am = 0; am < 4; am++)
                ldm_x4(A[am], base + (uint32_t)((aoffL + am * 16 * LDSROW + kb) * 2));
            uint32_t Bh[8];
#pragma unroll
            for (int pr = 0; pr < 2; pr++) {
                const uint32_t bd = (uint32_t)((boffL + pr * 16 * LDSROW + kb) * 2);
                ldm_x4(&Bh[pr * 4], base + (uint32_t)(G_ARR * 2) + bd);
            }
#pragma unroll
            for (int am = 0; am < 4; am++)
#pragma unroll
                for (int an = 0; an < 4; an++) {
                    mma16816(acc[am][an],
                             A[am][0], A[am][1], A[am][2], A[am][3],
                             Bh[an * 2], Bh[an * 2 + 1]);
                }
        }
        if (s < 31) g_sts1(gsm + ((s + 1) & 1) * 2 * G_ARR, lrow, lcol, rg);
    }

    // Epilogue
#pragma unroll
    for (int am = 0; am < 4; am++) {
        const int row = bm + wm + am * 16 + gid;
        bool v0 = true, v1 = true;
        if (rowmap) {
            v0 = (rowmap[row] >= 0);
            v1 = (rowmap[row + 8] >= 0);
        }
#pragma unroll
        for (int an = 0; an < 4; an++) {
            const int col = bn + wn + an * 8 + tig * 2;
            const float b0 = bias[col], b1 = bias[col + 1];
            float o00 = v0 ? (acc[am][an][0] + b0) * oscale : 0.f;
            float o01 = v0 ? (acc[am][an][1] + b1) * oscale : 0.f;
            float o10 = v1 ? (acc[am][an][2] + b0) * oscale : 0.f;
            float o11 = v1 ? (acc[am][an][3] + b1) * oscale : 0.f;
            if (Chi) {
                *(uint32_t*)&Chi[(size_t)row * 1024 + col] = pack_h2(o00, o01);
                *(uint32_t*)&Chi[(size_t)(row + 8) * 1024 + col] = pack_h2(o10, o11);
            } else {
                float2 f0 = {o00, o01}, f1 = {o10, o11};
                *(float2*)(Cf + (size_t)row * 1024 + col) = f0;
                *(float2*)(Cf + (size_t)(row + 8) * 1024 + col) = f1;
            }
        }
    }
}

// Fused Q/K/V projections. K/V slices early-exit tiles beyond the
// compacted row count (their outputs are never read).
__global__ __launch_bounds__(256) void qkv_gemm(
    const float* __restrict__ bq, const float* __restrict__ bk,
    const float* __restrict__ bv)
{
    extern __shared__ __half gsm[];
    if (blockIdx.z == 0) {
        gemm_body1(g_qsh, g_wqh, bq, nullptr, g_Qhi,
                   0.125f * 1.44269504f, nullptr, gsm);
    } else {
        const int bm    = blockIdx.y * 128;
        const int batch = bm / SQL;
        const int local = bm % SQL;
        const int nkp   = (g_knum[batch] + 63) & ~63;
        if (local >= nkp) return;   // whole tile unused downstream
        if (blockIdx.z == 1) {
            gemm_body1(g_ksh, g_wkh, bk, nullptr, g_Khi, 1.0f, g_rowmap, gsm);
        } else {
            gemm_body1(g_vsh, g_wvh, bv, nullptr, g_Vc, 1.0f, g_rowmap, gsm);
        }
    }
}

// O projection: f32 out.
__global__ __launch_bounds__(256) void o_gemm(
    const float* __restrict__ bo, float* __restrict__ out)
{
    extern __shared__ __half gsm[];
    gemm_body1(g_AOhi, g_woh, bo, out, nullptr, 1.0f, nullptr, gsm);
}

// ===========================================================================
// Prep: V transpose (fp16 -> fp16) -> Vt[b][h][d][key]
// ===========================================================================
__global__ __launch_bounds__(256) void prep_vt() {
    const int b = blockIdx.z, h = blockIdx.y, j0 = blockIdx.x * 64;
    const int nv  = g_knum[b];
    const int nkp = (nv + 63) & ~63;
    if (j0 >= nkp) return;
    __shared__ __half tile[64][72];
    const int t = threadIdx.x;
#pragma unroll
    for (int p = 0; p < 2; p++) {
        const int r = p * 32 + (t >> 3);
        const int c = (t & 7) * 8;
        uint4 v = *(const uint4*)&g_Vc[((size_t)b * SKL + j0 + r) * 1024 + h * 64 + c];
        *(uint4*)&tile[r][c] = v;
    }
    __syncthreads();
    const int d = t >> 2, jg = (t & 3) * 16;
    ushort hi[16];
#pragma unroll
    for (int i = 0; i < 16; i++) hi[i] = *(ushort*)&tile[jg + i][d];
    const size_t base = (((size_t)(b * NH + h)) * 64 + d) * NKMAX + j0 + jg;
    *(uint4*)&g_Vthi[base]     = *(uint4*)hi;
    *(uint4*)&g_Vthi[base + 8] = *(uint4*)&hi[8];
}

// ===========================================================================
// Flash attention: single-fp16 S + PV; half2-exp softmax; l via ones-MMA.
// ===========================================================================
#define FLDS   72
#define F_CH   (64 * FLDS)
#define F_BUF2 (2 * F_CH)
#define F_SMEM (2 * F_BUF2 * 2)   // 36864 bytes

#define ONES_H2 0x3C003C00u       // (1.0h, 1.0h)

__device__ __forceinline__ void f_ldg(int b, int h, int kt, int r, int c0,
                                      uint4* rg) {
    const size_t kb = ((size_t)b * SKL + kt + r) * 1024 + h * 64 + c0;
    rg[0] = *(const uint4*)&g_Khi[kb];
    rg[1] = *(const uint4*)&g_Khi[kb + 8];
    const size_t vb = (((size_t)(b * NH + h)) * 64 + r) * NKMAX + kt + c0;
    rg[2] = *(const uint4*)&g_Vthi[vb];
    rg[3] = *(const uint4*)&g_Vthi[vb + 8];
}

__device__ __forceinline__ void f_sts(__half* buf, int r, int c0,
                                      const uint4* rg) {
    const int o = r * FLDS + c0;
    *(uint4*)&buf[o]            = rg[0];
    *(uint4*)&buf[o + 8]        = rg[1];
    *(uint4*)&buf[F_CH + o]     = rg[2];
    *(uint4*)&buf[F_CH + o + 8] = rg[3];
}

__global__ __launch_bounds__(256) void flash_tc() {
    extern __shared__ __half fsm[];

    const int b = blockIdx.z, h = blockIdx.y, q0 = blockIdx.x * 128;
    const int tid = threadIdx.x;
    const int w = tid >> 5, lane = tid & 31;
    const int gid = lane >> 2, tig = lane & 3;

    const int nv  = g_knum[b];
    const int nkp = (nv + 63) & ~63;

    // ---- Stage Q through buffer 0 ----
    {
        const int r = tid >> 1, c0 = (tid & 1) * 32;
        const size_t gbase = ((size_t)b * SQL + q0 + r) * 1024 + h * 64 + c0;
        __half* qh = fsm + r * FLDS + c0;
#pragma unroll
        for (int u = 0; u < 4; u++)
            *(uint4*)&qh[u * 8] = *(const uint4*)&g_Qhi[gbase + u * 8];
    }
    __syncthreads();

    const uint32_t fb = s2u(fsm);
    uint32_t Qh[4][4];
    {
        const int qoffL = (w * 16 + (lane & 15)) * FLDS + (lane >> 4) * 8;
#pragma unroll
        for (int ks = 0; ks < 4; ks++)
            ldm_x4(Qh[ks], fb + (uint32_t)((qoffL + ks * 16) * 2));
    }
    __syncthreads();

    float Oa[8][4];
#pragma unroll
    for (int i = 0; i < 8; i++)
#pragma unroll
        for (int j = 0; j < 4; j++) Oa[i][j] = 0.f;
    float La[4];
#pragma unroll
    for (int j = 0; j < 4; j++) La[j] = 0.f;
    float m0 = -1e30f, m1 = -1e30f;

    const int lr = tid >> 2, lc0 = (tid & 3) * 16;
    const int foffL = ((lane & 7) | ((lane >> 1) & 8)) * FLDS
                      + ((lane >> 3) & 1) * 8;
    uint4 rg[4];
    f_ldg(b, h, 0, lr, lc0, rg);
    f_sts(fsm, lr, lc0, rg);

    int par = 0;
    for (int kt = 0; kt < nkp; kt += 64, par ^= 1) {
        __syncthreads();
        const bool more = (kt + 64) < nkp;
        if (more) f_ldg(b, h, kt + 64, lr, lc0, rg);

        const uint32_t base = fb + (uint32_t)(par * F_BUF2 * 2);

        // ---- S = Q K^T ----
        float S[8][4];
#pragma unroll
        for (int i = 0; i < 8; i++)
#pragma unroll
            for (int j = 0; j < 4; j++) S[i][j] = 0.f;

#pragma unroll
        for (int ks = 0; ks < 4; ks++) {
            const int kb = ks * 16;
#pragma unroll
            for (int pr = 0; pr < 4; pr++) {
                uint32_t kh[4];
                ldm_x4(kh, base + (uint32_t)((foffL + pr * 16 * FLDS + kb) * 2));
#pragma unroll
                for (int t2 = 0; t2 < 2; t2++) {
                    mma16816(S[pr * 2 + t2],
                             Qh[ks][0], Qh[ks][1], Qh[ks][2], Qh[ks][3],
                             kh[t2 * 2], kh[t2 * 2 + 1]);
                }
            }
        }

        // ---- tail mask ----
        if (kt + 64 > nv) {
#pragma unroll
            for (int nt = 0; nt < 8; nt++) {
                const int col = kt + nt * 8 + tig * 2;
                if (col >= nv)     { S[nt][0] = -1e30f; S[nt][2] = -1e30f; }
                if (col + 1 >= nv) { S[nt][1] = -1e30f; S[nt][3] = -1e30f; }
            }
        }

        // ---- online softmax (log2 domain; fp16x2 exp) ----
        float mx0 = -1e30f, mx1 = -1e30f;
#pragma unroll
        for (int nt = 0; nt < 8; nt++) {
            mx0 = fmaxf(mx0, fmaxf(S[nt][0], S[nt][1]));
            mx1 = fmaxf(mx1, fmaxf(S[nt][2], S[nt][3]));
        }
        mx0 = fmaxf(mx0, __shfl_xor_sync(0xffffffffu, mx0, 1));
        mx0 = fmaxf(mx0, __shfl_xor_sync(0xffffffffu, mx0, 2));
        mx1 = fmaxf(mx1, __shfl_xor_sync(0xffffffffu, mx1, 1));
        mx1 = fmaxf(mx1, __shfl_xor_sync(0xffffffffu, mx1, 2));

        const float mn0 = fmaxf(m0, mx0), mn1 = fmaxf(m1, mx1);
        const float corr0 = exp2f(m0 - mn0), corr1 = exp2f(m1 - mn1);
        m0 = mn0; m1 = mn1;

        uint32_t Ph[4][4];
#pragma unroll
        for (int nt = 0; nt < 8; nt++) {
            const uint32_t p01 = h2exp2(pack_h2(S[nt][0] - m0, S[nt][1] - m0));
            const uint32_t p23 = h2exp2(pack_h2(S[nt][2] - m1, S[nt][3] - m1));
            const int ks = nt >> 1;
            if ((nt & 1) == 0) { Ph[ks][0] = p01; Ph[ks][1] = p23; }
            else               { Ph[ks][2] = p01; Ph[ks][3] = p23; }
        }

#pragma unroll
        for (int nt = 0; nt < 8; nt++) {
            Oa[nt][0] *= corr0; Oa[nt][1] *= corr0;
            Oa[nt][2] *= corr1; Oa[nt][3] *= corr1;
        }
        La[0] *= corr0; La[1] *= corr0;
        La[2] *= corr1; La[3] *= corr1;

        // ---- l += P @ ones ----
#pragma unroll
        for (int ks = 0; ks < 4; ks++)
            mma16816(La, Ph[ks][0], Ph[ks][1], Ph[ks][2], Ph[ks][3],
                     ONES_H2, ONES_H2);

        // ---- O += P V ----
#pragma unroll
        for (int ks = 0; ks < 4; ks++) {
            const int kb = ks * 16;
#pragma unroll
            for (int pr = 0; pr < 4; pr++) {
                const uint32_t bd = (uint32_t)((foffL + pr * 16 * FLDS + kb) * 2);
                uint32_t vh[4];
                ldm_x4(vh, base + (uint32_t)(F_CH * 2) + bd);
#pragma unroll
                for (int t2 = 0; t2 < 2; t2++) {
                    mma16816(Oa[pr * 2 + t2],
                             Ph[ks][0], Ph[ks][1], Ph[ks][2], Ph[ks][3],
                             vh[t2 * 2], vh[t2 * 2 + 1]);
                }
            }
        }

        if (more) f_sts(fsm + (par ^ 1) * F_BUF2, lr, lc0, rg);
    }

    // ---- epilogue ----
    const float inv0 = 1.f / La[0], inv1 = 1.f / La[2];
    const int row0 = q0 + w * 16 + gid;
#pragma unroll
    for (int nt = 0; nt < 8; nt++) {
        const int col = h * 64 + nt * 8 + tig * 2;
        const size_t i0 = ((size_t)b * SQL + row0) * 1024 + col;
        const size_t i1 = ((size_t)b * SQL + row0 + 8) * 1024 + col;
        *(uint32_t*)&g_AOhi[i0] = pack_h2(Oa[nt][0] * inv0, Oa[nt][1] * inv0);
        *(uint32_t*)&g_AOhi[i1] = pack_h2(Oa[nt][2] * inv1, Oa[nt][3] * inv1);
    }
}

// ---------------------------------------------------------------------------
extern "C" void kernel_launch(void* const* d_in, const int* in_sizes, int n_in,
                              void* d_out, int out_size)
{
    const float* query = (const float*)d_in[0];
    const float* key   = (const float*)d_in[1];
    const float* value = (const float*)d_in[2];
    const int*   kpm   = (const int*)  d_in[3];
    const float* Wq    = (const float*)d_in[4];
    const float* bq    = (const float*)d_in[5];
    const float* Wk    = (const float*)d_in[6];
    const float* bk    = (const float*)d_in[7];
    const float* Wv    = (const float*)d_in[8];
    const float* bv    = (const float*)d_in[9];
    const float* Wo    = (const float*)d_in[10];
    const float* bo    = (const float*)d_in[11];
    float* out = (float*)d_out;

    cudaFuncSetAttribute(qkv_gemm, cudaFuncAttributeMaxDynamicSharedMemorySize,
                         G1_SMEM);
    cudaFuncSetAttribute(o_gemm, cudaFuncAttributeMaxDynamicSharedMemorySize,
                         G1_SMEM);
    cudaFuncSetAttribute(flash_tc, cudaFuncAttributeMaxDynamicSharedMemorySize,
                         F_SMEM);

    scan_mask<<<BB, 256>>>(kpm);

    const int gin = (int)(NIN / 1024);
    const int gw  = (int)(NW  / 1024);
    prep_in<<<dim3(gin, 3), 256>>>(query, key, value);
    prep_w<<<dim3(gw, 4), 256>>>(Wq, Wk, Wv, Wo);

    dim3 gQKV(DMODEL / 128, (BB * SQL) / 128, 3);   // (8, 64, 3)
    qkv_gemm<<<gQKV, 256, G1_SMEM>>>(bq, bk, bv);

    prep_vt<<<dim3(SKL / 64, NH, BB), 256>>>();

    flash_tc<<<dim3(SQL / 128, NH, BB), 256, F_SMEM>>>();

    dim3 gO(DMODEL / 128, (BB * SQL) / 128);        // (8, 64)
    o_gemm<<<gO, 256, G1_SMEM>>>(bo, out);
}